// round 10
// baseline (speedup 1.0000x reference)
#include <cuda_runtime.h>
#include <cstdint>

#define N_IN   128
#define N_HID  512
#define N_OUT  128
#define BATCH  128
#define LENGTH 1024
#define M_ROWS (BATCH * LENGTH)
#define T_SEG  256

#define OUT_LIST_OFF  67108864ull
#define OUT_FINAL_OFF 83886080ull

__device__ float g_Weff[N_HID * N_IN];
__device__ float g_beff[N_HID];

// ---------------- W_eff = W_ih @ W_in ; b_eff = W_ih@b_in + b_ih + b_hh -----
__global__ void weff_kernel(const float* __restrict__ Wih,
                            const float* __restrict__ Win,
                            const float* __restrict__ bin,
                            const float* __restrict__ bih,
                            const float* __restrict__ bhh) {
    const int j = blockIdx.x;
    const int i = threadIdx.x;
    __shared__ float sred[128];

    float acc = 0.0f;
    #pragma unroll 8
    for (int k = 0; k < N_HID; k++)
        acc = fmaf(Wih[j * N_HID + k], Win[k * N_IN + i], acc);
    g_Weff[j * N_IN + i] = acc;

    float accb = 0.0f;
    for (int k = i; k < N_HID; k += 128)
        accb = fmaf(Wih[j * N_HID + k], bin[k], accb);
    sred[i] = accb;
    __syncthreads();
    for (int st = 64; st > 0; st >>= 1) {
        if (i < st) sred[i] += sred[i + st];
        __syncthreads();
    }
    if (i == 0) g_beff[j] = sred[0] + bih[j] + bhh[j];
}

// ---------------- C[m][n] = sum_k A[m][k]*B[n][k] + bias[n] -----------------
__global__ __launch_bounds__(256) void gemm_tn_bias(
    const float* __restrict__ A, const float* __restrict__ B,
    const float* __restrict__ bias, float* __restrict__ C,
    int M, int N, int K)
{
    __shared__ float As[8][132];
    __shared__ float Bs[8][132];

    const int tid = threadIdx.x;
    const int m0 = blockIdx.x * 128;
    const int n0 = blockIdx.y * 128;
    const int tx = tid & 15;
    const int ty = tid >> 4;
    const int lr = tid >> 1;
    const int lc = (tid & 1) << 2;

    float acc[8][8];
    #pragma unroll
    for (int i = 0; i < 8; i++)
        #pragma unroll
        for (int j = 0; j < 8; j++) acc[i][j] = 0.0f;

    const float* Ap = &A[(size_t)(m0 + lr) * K + lc];
    const float* Bp = &B[(size_t)(n0 + lr) * K + lc];

    for (int k0 = 0; k0 < K; k0 += 8) {
        float4 av = *(const float4*)&Ap[k0];
        float4 bv = *(const float4*)&Bp[k0];
        As[lc + 0][lr] = av.x; As[lc + 1][lr] = av.y;
        As[lc + 2][lr] = av.z; As[lc + 3][lr] = av.w;
        Bs[lc + 0][lr] = bv.x; Bs[lc + 1][lr] = bv.y;
        Bs[lc + 2][lr] = bv.z; Bs[lc + 3][lr] = bv.w;
        __syncthreads();

        #pragma unroll
        for (int kk = 0; kk < 8; kk++) {
            float4 a0 = *(const float4*)&As[kk][ty * 8];
            float4 a1 = *(const float4*)&As[kk][ty * 8 + 4];
            float4 b0 = *(const float4*)&Bs[kk][tx * 8];
            float4 b1 = *(const float4*)&Bs[kk][tx * 8 + 4];
            float ra[8] = {a0.x, a0.y, a0.z, a0.w, a1.x, a1.y, a1.z, a1.w};
            float rb[8] = {b0.x, b0.y, b0.z, b0.w, b1.x, b1.y, b1.z, b1.w};
            #pragma unroll
            for (int i = 0; i < 8; i++)
                #pragma unroll
                for (int j = 0; j < 8; j++)
                    acc[i][j] = fmaf(ra[i], rb[j], acc[i][j]);
        }
        __syncthreads();
    }

    float bs[8];
    #pragma unroll
    for (int j = 0; j < 8; j++) bs[j] = bias[n0 + tx * 8 + j];

    #pragma unroll
    for (int i = 0; i < 8; i++) {
        float* crow = &C[(size_t)(m0 + ty * 8 + i) * N + n0 + tx * 8];
        *(float4*)&crow[0] = make_float4(acc[i][0] + bs[0], acc[i][1] + bs[1],
                                         acc[i][2] + bs[2], acc[i][3] + bs[3]);
        *(float4*)&crow[4] = make_float4(acc[i][4] + bs[4], acc[i][5] + bs[5],
                                         acc[i][6] + bs[6], acc[i][7] + bs[7]);
    }
}

// ---------------- recurrence segment: 512 threads, shuffle k-reduction ------
// 16 clusters x 8 CTAs x 512 threads. CTA rank r owns h rows [64r,64r+64).
// warp = rt (4 rows), lane = kc*2+bt: thread tile 4 rows x 4 batches x 32 k.
// Butterfly shfl reduces 16 k-chunk partials; lane kc keeps result
// (row rt*4+(kc&3), batch bt*4+(kc>>2)); h_old kept in register.
#define RP      68          // W_T row stride (words)
#define BP      12          // H batch stride (words)
#define WT_SZ   (512 * RP)
#define HT_SZ   (512 * BP)
#define H_OFF   WT_SZ
#define STG_OFF (H_OFF + 2 * HT_SZ)
#define SM_FLOATS (STG_OFF + 64 * BP)

__device__ __forceinline__ uint32_t smem_u32(const void* p) {
    uint32_t a;
    asm("{ .reg .u64 t; cvta.to.shared.u64 t, %1; cvt.u32.u64 %0, t; }"
        : "=r"(a) : "l"(p));
    return a;
}

__global__ __cluster_dims__(8, 1, 1) __launch_bounds__(512, 1)
void rec_kernel(const float* __restrict__ Whh, const float* __restrict__ h0,
                float* __restrict__ hidden, float* __restrict__ hfinal,
                int t0)
{
    extern __shared__ float sm[];
    float* W_T = sm;             // [512 k][RP] (rows transposed)
    float* H   = sm + H_OFF;     // [2][512 k][BP]
    float* stg = sm + STG_OFF;   // [64 rows][BP]

    const int tid = threadIdx.x;
    uint32_t rank;
    asm("mov.u32 %0, %%cluster_ctarank;" : "=r"(rank));
    const int grp  = blockIdx.x >> 3;
    const int row0 = (int)rank * 64;
    const int b0   = grp * 8;

    // W transpose: Whh[row0+j][k] -> W_T[k][j]
    for (int idx = tid; idx < 64 * 128; idx += 512) {
        int j = idx >> 7, k4 = (idx & 127) << 2;
        float4 w = *(const float4*)&Whh[(size_t)(row0 + j) * N_HID + k4];
        W_T[(k4 + 0) * RP + j] = w.x;
        W_T[(k4 + 1) * RP + j] = w.y;
        W_T[(k4 + 2) * RP + j] = w.z;
        W_T[(k4 + 3) * RP + j] = w.w;
    }
    // h(t0-1) transposed into buffer (t0&1)
    {
        float* Hb = &H[(t0 & 1) * HT_SZ];
        for (int idx = tid; idx < 8 * 128; idx += 512) {
            int b = idx >> 7, k4 = (idx & 127) << 2;
            const float* src = (t0 == 0)
                ? &h0[(size_t)(b0 + b) * N_HID + k4]
                : &hidden[((size_t)(b0 + b) * LENGTH + (t0 - 1)) * N_HID + k4];
            float4 h = *(const float4*)src;
            Hb[(k4 + 0) * BP + b] = h.x;
            Hb[(k4 + 1) * BP + b] = h.y;
            Hb[(k4 + 2) * BP + b] = h.z;
            Hb[(k4 + 3) * BP + b] = h.w;
        }
    }

    // thread coords
    const int rt   = tid >> 5;         // warp id 0..15 -> rows rt*4..rt*4+3
    const int lane = tid & 31;
    const int kc   = lane >> 1;        // k-chunk 0..15
    const int bt   = lane & 1;         // batch half
    // owned result after reduction:
    const int row_l = rt * 4 + (kc & 3);
    const int bat_l = bt * 4 + (kc >> 2);
    const int absrow = row0 + row_l;
    const int bglob  = b0 + bat_l;

    // push decomposition: 1024 v4 = 8 ranks x 64 rows x 2 halves; 2/thread
    const int pr   = tid >> 8;                  // idx and idx+512 -> ranks pr*? :
    const int prow = (tid & 255) >> 2;          // 0..63
    const int pq   = (tid >> 1) & 1;            // half
    // idx = tid -> rank = tid>>7? use explicit: item i covers rank (pr + 4*i)? 
    // simpler: item0 rank = tid>>7 (0..3), item1 rank = (tid>>7)+4
    const int pr0   = tid >> 7;                 // 0..3
    const int prow2 = (tid & 127) >> 1;         // 0..63
    const int pq2   = tid & 1;
    const float*   pSrc = &stg[prow2 * BP + pq2 * 4];
    const uint32_t dOffBase = (uint32_t)(((row0 + prow2) * BP + pq2 * 4) * 4);
    (void)pr; (void)prow; (void)pq;

    uint32_t Hbase = smem_u32(H);
    uint32_t peer[8];
    #pragma unroll
    for (int r = 0; r < 8; r++)
        asm("mapa.shared::cluster.u32 %0, %1, %2;"
            : "=r"(peer[r]) : "r"(Hbase), "r"(r));

    __syncthreads();

    // h_old register
    float h_reg = H[(t0 & 1) * HT_SZ + absrow * BP + bat_l];

    const int tend = t0 + T_SEG;
    for (int t = t0; t < tend; t++) {
        const int p = t & 1;
        const int q = p ^ 1;
        const float* Hp = &H[p * HT_SZ];

        // prefetch Z for owned (row,batch)
        size_t off = ((size_t)bglob * LENGTH + t) * N_HID + absrow;
        float z = hidden[off];

        // GEMV partials: v[x] , x = i + 4*j  (i=row idx 0..3, j=batch idx 0..3)
        float v[16];
        #pragma unroll
        for (int x = 0; x < 16; x++) v[x] = 0.0f;

        #pragma unroll 4
        for (int m = 0; m < 32; m++) {
            int k = kc + (m << 4);
            float4 w = *(const float4*)&W_T[k * RP + rt * 4];
            float4 h = *(const float4*)&Hp[k * BP + bt * 4];
            float wv[4] = {w.x, w.y, w.z, w.w};
            float hv[4] = {h.x, h.y, h.z, h.w};
            #pragma unroll
            for (int j = 0; j < 4; j++)
                #pragma unroll
                for (int i = 0; i < 4; i++)
                    v[i + 4 * j] = fmaf(wv[i], hv[j], v[i + 4 * j]);
        }

        // butterfly all-to-one: lane kc ends with sum for x = kc
        #pragma unroll
        for (int bst = 0; bst < 4; bst++) {
            const int msk  = 2 << bst;            // lane xor (kc bit bst)
            const int keep = (kc >> bst) & 1;
            const int n    = 16 >> (bst + 1);
            #pragma unroll
            for (int s = 0; s < n; s++) {
                float e = __shfl_xor_sync(0xffffffffu, v[2 * s],     msk);
                float o = __shfl_xor_sync(0xffffffffu, v[2 * s + 1], msk);
                v[s] = keep ? (v[2 * s + 1] + o) : (v[2 * s] + e);
            }
        }
        float sum = v[0];

        float hn = 0.9f * h_reg + 0.1f * fmaxf(z + sum, 0.0f);
        h_reg = hn;

        // stage for push (scalar STS, ~2-way conflicts)
        stg[row_l * BP + bat_l] = hn;
        __syncthreads();

        // push to all 8 ranks' buffer q (2 float4 DSMEM stores/thread)
        const uint32_t dOff = (uint32_t)(q * HT_SZ * 4) + dOffBase;
        float4 v4 = *(const float4*)pSrc;
        #pragma unroll
        for (int i = 0; i < 2; i++) {
            int r = pr0 + i * 4;
            asm volatile("st.shared::cluster.v4.f32 [%0], {%1,%2,%3,%4};"
                         :: "r"(peer[r] + dOff),
                            "f"(v4.x), "f"(v4.y), "f"(v4.z), "f"(v4.w)
                         : "memory");
        }
        asm volatile("barrier.cluster.arrive.aligned;" ::: "memory");

        // global stores in barrier-drain shadow
        hidden[off] = hn;
        if (t == LENGTH - 1)
            hfinal[(size_t)bglob * N_HID + absrow] = hn;

        asm volatile("barrier.cluster.wait.aligned;" ::: "memory");
    }
}

extern "C" void kernel_launch(void* const* d_in, const int* in_sizes, int n_in,
                              void* d_out, int out_size) {
    const float* u    = (const float*)d_in[0];
    const float* h0   = (const float*)d_in[1];
    const float* Win  = (const float*)d_in[2];
    const float* bin  = (const float*)d_in[3];
    const float* Wih  = (const float*)d_in[4];
    const float* bih  = (const float*)d_in[5];
    const float* Whh  = (const float*)d_in[6];
    const float* bhh  = (const float*)d_in[7];
    const float* Wout = (const float*)d_in[8];
    const float* bout = (const float*)d_in[9];

    float* out     = (float*)d_out;
    float* hidden  = out;
    float* outlist = out + OUT_LIST_OFF;
    float* hfinal  = out + OUT_FINAL_OFF;

    weff_kernel<<<N_HID, 128>>>(Wih, Win, bin, bih, bhh);

    {
        float* dWeff; float* dbeff;
        cudaGetSymbolAddress((void**)&dWeff, g_Weff);
        cudaGetSymbolAddress((void**)&dbeff, g_beff);
        dim3 grid(M_ROWS / 128, N_HID / 128);
        gemm_tn_bias<<<grid, 256>>>(u, dWeff, dbeff, hidden,
                                    M_ROWS, N_HID, N_IN);
    }

    {
        static int smem_set = 0;
        int smem = SM_FLOATS * sizeof(float);  // 191488 + stg = ~194.6 KB
        if (!smem_set) {
            cudaFuncSetAttribute(rec_kernel,
                                 cudaFuncAttributeMaxDynamicSharedMemorySize,
                                 smem);
            smem_set = 1;
        }
        for (int t0 = 0; t0 < LENGTH; t0 += T_SEG)
            rec_kernel<<<128, 512, smem>>>(Whh, h0, hidden, hfinal, t0);
    }

    {
        dim3 grid(M_ROWS / 128, N_OUT / 128);
        gemm_tn_bias<<<grid, 256>>>(hidden, Wout, bout, outlist,
                                    M_ROWS, N_OUT, N_HID);
    }
}

// round 11
// speedup vs baseline: 1.2073x; 1.2073x over previous
#include <cuda_runtime.h>
#include <cstdint>

#define N_IN   128
#define N_HID  512
#define N_OUT  128
#define BATCH  128
#define LENGTH 1024
#define M_ROWS (BATCH * LENGTH)
#define T_SEG  256

#define OUT_LIST_OFF  67108864ull
#define OUT_FINAL_OFF 83886080ull

__device__ float g_Weff[N_HID * N_IN];
__device__ float g_beff[N_HID];

// ---------------- W_eff = W_ih @ W_in ; b_eff = W_ih@b_in + b_ih + b_hh -----
__global__ void weff_kernel(const float* __restrict__ Wih,
                            const float* __restrict__ Win,
                            const float* __restrict__ bin,
                            const float* __restrict__ bih,
                            const float* __restrict__ bhh) {
    const int j = blockIdx.x;
    const int i = threadIdx.x;
    __shared__ float sred[128];

    float acc = 0.0f;
    #pragma unroll 8
    for (int k = 0; k < N_HID; k++)
        acc = fmaf(Wih[j * N_HID + k], Win[k * N_IN + i], acc);
    g_Weff[j * N_IN + i] = acc;

    float accb = 0.0f;
    for (int k = i; k < N_HID; k += 128)
        accb = fmaf(Wih[j * N_HID + k], bin[k], accb);
    sred[i] = accb;
    __syncthreads();
    for (int st = 64; st > 0; st >>= 1) {
        if (i < st) sred[i] += sred[i + st];
        __syncthreads();
    }
    if (i == 0) g_beff[j] = sred[0] + bih[j] + bhh[j];
}

// ---------------- C[m][n] = sum_k A[m][k]*B[n][k] + bias[n] -----------------
__global__ __launch_bounds__(256) void gemm_tn_bias(
    const float* __restrict__ A, const float* __restrict__ B,
    const float* __restrict__ bias, float* __restrict__ C,
    int M, int N, int K)
{
    __shared__ float As[8][132];
    __shared__ float Bs[8][132];

    const int tid = threadIdx.x;
    const int m0 = blockIdx.x * 128;
    const int n0 = blockIdx.y * 128;
    const int tx = tid & 15;
    const int ty = tid >> 4;
    const int lr = tid >> 1;
    const int lc = (tid & 1) << 2;

    float acc[8][8];
    #pragma unroll
    for (int i = 0; i < 8; i++)
        #pragma unroll
        for (int j = 0; j < 8; j++) acc[i][j] = 0.0f;

    const float* Ap = &A[(size_t)(m0 + lr) * K + lc];
    const float* Bp = &B[(size_t)(n0 + lr) * K + lc];

    for (int k0 = 0; k0 < K; k0 += 8) {
        float4 av = *(const float4*)&Ap[k0];
        float4 bv = *(const float4*)&Bp[k0];
        As[lc + 0][lr] = av.x; As[lc + 1][lr] = av.y;
        As[lc + 2][lr] = av.z; As[lc + 3][lr] = av.w;
        Bs[lc + 0][lr] = bv.x; Bs[lc + 1][lr] = bv.y;
        Bs[lc + 2][lr] = bv.z; Bs[lc + 3][lr] = bv.w;
        __syncthreads();

        #pragma unroll
        for (int kk = 0; kk < 8; kk++) {
            float4 a0 = *(const float4*)&As[kk][ty * 8];
            float4 a1 = *(const float4*)&As[kk][ty * 8 + 4];
            float4 b0 = *(const float4*)&Bs[kk][tx * 8];
            float4 b1 = *(const float4*)&Bs[kk][tx * 8 + 4];
            float ra[8] = {a0.x, a0.y, a0.z, a0.w, a1.x, a1.y, a1.z, a1.w};
            float rb[8] = {b0.x, b0.y, b0.z, b0.w, b1.x, b1.y, b1.z, b1.w};
            #pragma unroll
            for (int i = 0; i < 8; i++)
                #pragma unroll
                for (int j = 0; j < 8; j++)
                    acc[i][j] = fmaf(ra[i], rb[j], acc[i][j]);
        }
        __syncthreads();
    }

    float bs[8];
    #pragma unroll
    for (int j = 0; j < 8; j++) bs[j] = bias[n0 + tx * 8 + j];

    #pragma unroll
    for (int i = 0; i < 8; i++) {
        float* crow = &C[(size_t)(m0 + ty * 8 + i) * N + n0 + tx * 8];
        *(float4*)&crow[0] = make_float4(acc[i][0] + bs[0], acc[i][1] + bs[1],
                                         acc[i][2] + bs[2], acc[i][3] + bs[3]);
        *(float4*)&crow[4] = make_float4(acc[i][4] + bs[4], acc[i][5] + bs[5],
                                         acc[i][6] + bs[6], acc[i][7] + bs[7]);
    }
}

// ---------------- recurrence: tensor-core (mma.sync tf32 x3) ----------------
// 16 clusters x 8 CTAs x 256 threads. CTA rank r: rows [64r,64r+64), 8 batches.
// Warp w: m-tile mt=w&3 (16 rows), k-half kh=w>>2 (256 k). 32 k-steps of
// m16n8k8, 3xTF32 split, fp32 accum. k-half partials reduced via SMEM scratch;
// finalize by warps 0-3; exchange = stage -> float4 DSMEM all-to-all + one
// barrier.cluster per step.
#define WST   516                      // W row stride (floats)
#define W_SZ  (64 * WST)               // 33024
#define HT_SZ (512 * 8)                // 4096 floats per h buffer
#define H_OFF W_SZ
#define SCR_OFF (H_OFF + 2 * HT_SZ)    // 41216
#define STG_OFF (SCR_OFF + 512)        // 41728
#define SM_FLOATS (STG_OFF + 512)      // 42240 -> 168960 B

__device__ __forceinline__ uint32_t smem_u32(const void* p) {
    uint32_t a;
    asm("{ .reg .u64 t; cvta.to.shared.u64 t, %1; cvt.u32.u64 %0, t; }"
        : "=r"(a) : "l"(p));
    return a;
}
__device__ __forceinline__ uint32_t f2tf(float x) {
    uint32_t r;
    asm("cvt.rna.tf32.f32 %0, %1;" : "=r"(r) : "f"(x));
    return r;
}
__device__ __forceinline__ void mma_tf32(float* d, uint32_t a0, uint32_t a1,
                                         uint32_t a2, uint32_t a3,
                                         uint32_t b0, uint32_t b1) {
    asm volatile(
        "mma.sync.aligned.m16n8k8.row.col.f32.tf32.tf32.f32 "
        "{%0,%1,%2,%3}, {%4,%5,%6,%7}, {%8,%9}, {%0,%1,%2,%3};"
        : "+f"(d[0]), "+f"(d[1]), "+f"(d[2]), "+f"(d[3])
        : "r"(a0), "r"(a1), "r"(a2), "r"(a3), "r"(b0), "r"(b1));
}

__global__ __cluster_dims__(8, 1, 1) __launch_bounds__(256, 1)
void rec_kernel(const float* __restrict__ Whh, const float* __restrict__ h0,
                float* __restrict__ hidden, float* __restrict__ hfinal,
                int t0)
{
    extern __shared__ float sm[];
    float* W_s = sm;             // [64 rows][WST]
    float* H   = sm + H_OFF;     // [2][512 k][8 batch]
    float* scr = sm + SCR_OFF;   // [4 mt][32 lane][4]
    float* stg = sm + STG_OFF;   // [64 rows][8 batch]

    const int tid = threadIdx.x;
    uint32_t rank;
    asm("mov.u32 %0, %%cluster_ctarank;" : "=r"(rank));
    const int grp  = blockIdx.x >> 3;
    const int row0 = (int)rank * 64;
    const int b0   = grp * 8;

    // W rows [row0,row0+64) row-major
    for (int idx = tid; idx < 64 * 128; idx += 256) {
        int r = idx >> 7, k4 = (idx & 127) << 2;
        *(float4*)&W_s[r * WST + k4] =
            *(const float4*)&Whh[(size_t)(row0 + r) * N_HID + k4];
    }
    // h(t0-1) -> H buffer (t0&1), layout [k][batch]
    {
        float* Hb = &H[(t0 & 1) * HT_SZ];
        for (int idx = tid; idx < 8 * 128; idx += 256) {
            int b = idx >> 7, k4 = (idx & 127) << 2;
            const float* src = (t0 == 0)
                ? &h0[(size_t)(b0 + b) * N_HID + k4]
                : &hidden[((size_t)(b0 + b) * LENGTH + (t0 - 1)) * N_HID + k4];
            float4 h = *(const float4*)src;
            Hb[(k4 + 0) * 8 + b] = h.x;
            Hb[(k4 + 1) * 8 + b] = h.y;
            Hb[(k4 + 2) * 8 + b] = h.z;
            Hb[(k4 + 3) * 8 + b] = h.w;
        }
    }

    const int w    = tid >> 5;
    const int lane = tid & 31;
    const int mt   = w & 3;        // m-tile
    const int kh   = w >> 2;       // k-half
    const int g    = lane >> 2;    // groupID
    const int tg   = lane & 3;     // thread-in-group

    // finalize coords (kh==0 warps): rows rA=mt*16+g, rB=rA+8; batches 2tg,2tg+1
    const int rA = mt * 16 + g;
    const int rB = rA + 8;
    const int absA = row0 + rA;
    const int absB = row0 + rB;
    const int ba = b0 + 2 * tg;

    // push decomposition: 1024 float4 = 8 ranks x 128 f4; 4 per thread
    const int f4  = tid & 127;
    const int rb  = tid >> 7;
    const float* pSrc = &stg[f4 * 4];
    const uint32_t dOffBase = (uint32_t)((row0 * 8 + f4 * 4) * 4);

    uint32_t Hbase = smem_u32(H);
    uint32_t peer[8];
    #pragma unroll
    for (int r = 0; r < 8; r++)
        asm("mapa.shared::cluster.u32 %0, %1, %2;"
            : "=r"(peer[r]) : "r"(Hbase), "r"(r));

    __syncthreads();

    const int tend = t0 + T_SEG;
    for (int t = t0; t < tend; t++) {
        const int p = t & 1;
        const int q = p ^ 1;
        const float* Hp = &H[p * HT_SZ];

        // Z prefetch (finalize warps only) — hides under MMA
        float z0, z1, z2, z3;
        size_t offA0 = 0, offA1 = 0, offB0 = 0, offB1 = 0;
        if (kh == 0) {
            offA0 = ((size_t)ba * LENGTH + t) * N_HID + absA;
            offA1 = offA0 + (size_t)LENGTH * N_HID;
            offB0 = offA0 + 8;
            offB1 = offA1 + 8;
            z0 = hidden[offA0]; z1 = hidden[offA1];
            z2 = hidden[offB0]; z3 = hidden[offB1];
        }

        // MMA mainloop: D = Whi*Hhi + Whi*Hlo + Wlo*Hhi over 32 k-steps
        float acc0[4] = {0, 0, 0, 0};
        float acc1[4] = {0, 0, 0, 0};
        float acc2[4] = {0, 0, 0, 0};
        const float* Wbase = &W_s[(mt * 16 + g) * WST + kh * 256 + tg];
        const float* Bbase = &Hp[(kh * 256 + tg) * 8 + g];

        #pragma unroll 8
        for (int ks = 0; ks < 32; ks++) {
            float a0f = Wbase[ks * 8];
            float a1f = Wbase[ks * 8 + 8 * WST];
            float a2f = Wbase[ks * 8 + 4];
            float a3f = Wbase[ks * 8 + 8 * WST + 4];
            float b0f = Bbase[ks * 64];
            float b1f = Bbase[ks * 64 + 32];

            uint32_t a0h = f2tf(a0f), a1h = f2tf(a1f);
            uint32_t a2h = f2tf(a2f), a3h = f2tf(a3f);
            uint32_t a0l = f2tf(a0f - __uint_as_float(a0h));
            uint32_t a1l = f2tf(a1f - __uint_as_float(a1h));
            uint32_t a2l = f2tf(a2f - __uint_as_float(a2h));
            uint32_t a3l = f2tf(a3f - __uint_as_float(a3h));
            uint32_t b0h = f2tf(b0f), b1h = f2tf(b1f);
            uint32_t b0l = f2tf(b0f - __uint_as_float(b0h));
            uint32_t b1l = f2tf(b1f - __uint_as_float(b1h));

            mma_tf32(acc0, a0h, a1h, a2h, a3h, b0h, b1h);
            mma_tf32(acc1, a0h, a1h, a2h, a3h, b0l, b1l);
            mma_tf32(acc2, a0l, a1l, a2l, a3l, b0h, b1h);
        }

        float c[4];
        #pragma unroll
        for (int i = 0; i < 4; i++) c[i] = acc0[i] + acc1[i] + acc2[i];

        // k-half reduce: kh=1 stores, kh=0 adds
        if (kh == 1)
            *(float4*)&scr[(mt * 32 + lane) * 4] =
                make_float4(c[0], c[1], c[2], c[3]);
        __syncthreads();

        if (kh == 0) {
            float4 o = *(const float4*)&scr[(mt * 32 + lane) * 4];
            c[0] += o.x; c[1] += o.y; c[2] += o.z; c[3] += o.w;

            float2 hA = *(const float2*)&Hp[absA * 8 + 2 * tg];
            float2 hB = *(const float2*)&Hp[absB * 8 + 2 * tg];
            float hn0 = 0.9f * hA.x + 0.1f * fmaxf(z0 + c[0], 0.0f);
            float hn1 = 0.9f * hA.y + 0.1f * fmaxf(z1 + c[1], 0.0f);
            float hn2 = 0.9f * hB.x + 0.1f * fmaxf(z2 + c[2], 0.0f);
            float hn3 = 0.9f * hB.y + 0.1f * fmaxf(z3 + c[3], 0.0f);

            *(float2*)&stg[rA * 8 + 2 * tg] = make_float2(hn0, hn1);
            *(float2*)&stg[rB * 8 + 2 * tg] = make_float2(hn2, hn3);
            z0 = hn0; z1 = hn1; z2 = hn2; z3 = hn3;   // reuse regs for store
        }
        __syncthreads();

        // push stage (2KB) to all 8 ranks' buffer q
        const uint32_t dOff = (uint32_t)(q * HT_SZ * 4) + dOffBase;
        float4 v4 = *(const float4*)pSrc;
        #pragma unroll
        for (int i = 0; i < 4; i++) {
            int r = rb + 2 * i;
            asm volatile("st.shared::cluster.v4.f32 [%0], {%1,%2,%3,%4};"
                         :: "r"(peer[r] + dOff),
                            "f"(v4.x), "f"(v4.y), "f"(v4.z), "f"(v4.w)
                         : "memory");
        }
        asm volatile("barrier.cluster.arrive.aligned;" ::: "memory");

        // global stores in barrier-drain shadow
        if (kh == 0) {
            hidden[offA0] = z0; hidden[offA1] = z1;
            hidden[offB0] = z2; hidden[offB1] = z3;
            if (t == LENGTH - 1) {
                hfinal[(size_t)ba * N_HID + absA] = z0;
                hfinal[(size_t)(ba + 1) * N_HID + absA] = z1;
                hfinal[(size_t)ba * N_HID + absB] = z2;
                hfinal[(size_t)(ba + 1) * N_HID + absB] = z3;
            }
        }
        asm volatile("barrier.cluster.wait.aligned;" ::: "memory");
    }
}

extern "C" void kernel_launch(void* const* d_in, const int* in_sizes, int n_in,
                              void* d_out, int out_size) {
    const float* u    = (const float*)d_in[0];
    const float* h0   = (const float*)d_in[1];
    const float* Win  = (const float*)d_in[2];
    const float* bin  = (const float*)d_in[3];
    const float* Wih  = (const float*)d_in[4];
    const float* bih  = (const float*)d_in[5];
    const float* Whh  = (const float*)d_in[6];
    const float* bhh  = (const float*)d_in[7];
    const float* Wout = (const float*)d_in[8];
    const float* bout = (const float*)d_in[9];

    float* out     = (float*)d_out;
    float* hidden  = out;
    float* outlist = out + OUT_LIST_OFF;
    float* hfinal  = out + OUT_FINAL_OFF;

    weff_kernel<<<N_HID, 128>>>(Wih, Win, bin, bih, bhh);

    {
        float* dWeff; float* dbeff;
        cudaGetSymbolAddress((void**)&dWeff, g_Weff);
        cudaGetSymbolAddress((void**)&dbeff, g_beff);
        dim3 grid(M_ROWS / 128, N_HID / 128);
        gemm_tn_bias<<<grid, 256>>>(u, dWeff, dbeff, hidden,
                                    M_ROWS, N_HID, N_IN);
    }

    {
        static int smem_set = 0;
        int smem = SM_FLOATS * sizeof(float);  // 168960
        if (!smem_set) {
            cudaFuncSetAttribute(rec_kernel,
                                 cudaFuncAttributeMaxDynamicSharedMemorySize,
                                 smem);
            smem_set = 1;
        }
        for (int t0 = 0; t0 < LENGTH; t0 += T_SEG)
            rec_kernel<<<128, 256, smem>>>(Whh, h0, hidden, hfinal, t0);
    }

    {
        dim3 grid(M_ROWS / 128, N_OUT / 128);
        gemm_tn_bias<<<grid, 256>>>(hidden, Wout, bout, outlist,
                                    M_ROWS, N_OUT, N_HID);
    }
}

// round 12
// speedup vs baseline: 1.7420x; 1.4429x over previous
#include <cuda_runtime.h>
#include <cstdint>

#define N_IN   128
#define N_HID  512
#define N_OUT  128
#define BATCH  128
#define LENGTH 1024
#define M_ROWS (BATCH * LENGTH)
#define T_SEG  256

#define OUT_LIST_OFF  67108864ull
#define OUT_FINAL_OFF 83886080ull

__device__ float g_Weff[N_HID * N_IN];
__device__ float g_beff[N_HID];

// ---------------- W_eff = W_ih @ W_in ; b_eff = W_ih@b_in + b_ih + b_hh -----
__global__ void weff_kernel(const float* __restrict__ Wih,
                            const float* __restrict__ Win,
                            const float* __restrict__ bin,
                            const float* __restrict__ bih,
                            const float* __restrict__ bhh) {
    const int j = blockIdx.x;
    const int i = threadIdx.x;
    __shared__ float sred[128];

    float acc = 0.0f;
    #pragma unroll 8
    for (int k = 0; k < N_HID; k++)
        acc = fmaf(Wih[j * N_HID + k], Win[k * N_IN + i], acc);
    g_Weff[j * N_IN + i] = acc;

    float accb = 0.0f;
    for (int k = i; k < N_HID; k += 128)
        accb = fmaf(Wih[j * N_HID + k], bin[k], accb);
    sred[i] = accb;
    __syncthreads();
    for (int st = 64; st > 0; st >>= 1) {
        if (i < st) sred[i] += sred[i + st];
        __syncthreads();
    }
    if (i == 0) g_beff[j] = sred[0] + bih[j] + bhh[j];
}

// ---------------- C[m][n] = sum_k A[m][k]*B[n][k] + bias[n] -----------------
__global__ __launch_bounds__(256) void gemm_tn_bias(
    const float* __restrict__ A, const float* __restrict__ B,
    const float* __restrict__ bias, float* __restrict__ C,
    int M, int N, int K)
{
    __shared__ float As[8][132];
    __shared__ float Bs[8][132];

    const int tid = threadIdx.x;
    const int m0 = blockIdx.x * 128;
    const int n0 = blockIdx.y * 128;
    const int tx = tid & 15;
    const int ty = tid >> 4;
    const int lr = tid >> 1;
    const int lc = (tid & 1) << 2;

    float acc[8][8];
    #pragma unroll
    for (int i = 0; i < 8; i++)
        #pragma unroll
        for (int j = 0; j < 8; j++) acc[i][j] = 0.0f;

    const float* Ap = &A[(size_t)(m0 + lr) * K + lc];
    const float* Bp = &B[(size_t)(n0 + lr) * K + lc];

    for (int k0 = 0; k0 < K; k0 += 8) {
        float4 av = *(const float4*)&Ap[k0];
        float4 bv = *(const float4*)&Bp[k0];
        As[lc + 0][lr] = av.x; As[lc + 1][lr] = av.y;
        As[lc + 2][lr] = av.z; As[lc + 3][lr] = av.w;
        Bs[lc + 0][lr] = bv.x; Bs[lc + 1][lr] = bv.y;
        Bs[lc + 2][lr] = bv.z; Bs[lc + 3][lr] = bv.w;
        __syncthreads();

        #pragma unroll
        for (int kk = 0; kk < 8; kk++) {
            float4 a0 = *(const float4*)&As[kk][ty * 8];
            float4 a1 = *(const float4*)&As[kk][ty * 8 + 4];
            float4 b0 = *(const float4*)&Bs[kk][tx * 8];
            float4 b1 = *(const float4*)&Bs[kk][tx * 8 + 4];
            float ra[8] = {a0.x, a0.y, a0.z, a0.w, a1.x, a1.y, a1.z, a1.w};
            float rb[8] = {b0.x, b0.y, b0.z, b0.w, b1.x, b1.y, b1.z, b1.w};
            #pragma unroll
            for (int i = 0; i < 8; i++)
                #pragma unroll
                for (int j = 0; j < 8; j++)
                    acc[i][j] = fmaf(ra[i], rb[j], acc[i][j]);
        }
        __syncthreads();
    }

    float bs[8];
    #pragma unroll
    for (int j = 0; j < 8; j++) bs[j] = bias[n0 + tx * 8 + j];

    #pragma unroll
    for (int i = 0; i < 8; i++) {
        float* crow = &C[(size_t)(m0 + ty * 8 + i) * N + n0 + tx * 8];
        *(float4*)&crow[0] = make_float4(acc[i][0] + bs[0], acc[i][1] + bs[1],
                                         acc[i][2] + bs[2], acc[i][3] + bs[3]);
        *(float4*)&crow[4] = make_float4(acc[i][4] + bs[4], acc[i][5] + bs[5],
                                         acc[i][6] + bs[6], acc[i][7] + bs[7]);
    }
}

// ---------------- recurrence: bf16x3 mma, hoisted splits ---------------------
// 16 clusters x 8 CTAs x 256 threads. Warp w: m-tile mt=w&3, k-half kh=w>>2.
// W pre-split (per segment) into packed-bf16 hi/lo [64 rows][260 k2].
// H pre-split (per step) into packed-bf16 hi/lo [256 k2][8 batch].
// 16 x m16n8k16 bf16 MMA x3 per warp per step; kh-reduce via scratch;
// exchange = stage -> float4 DSMEM all-to-all -> barrier.cluster.
#define WPST    260                        // packed W row stride (words)
#define WHI_OFF 0
#define WLO_OFF 16640
#define HF_OFF  33280                      // fp32 H ping-pong [2][512][8]
#define HT_SZ   4096
#define HHI_OFF 41472                      // packed bf16 hi [256][8]
#define HLO_OFF 43520
#define SCR_OFF 45568
#define STG_OFF 46080
#define SM_WORDS 46592                     // *4 = 186368 B

__device__ __forceinline__ uint32_t smem_u32(const void* p) {
    uint32_t a;
    asm("{ .reg .u64 t; cvta.to.shared.u64 t, %1; cvt.u32.u64 %0, t; }"
        : "=r"(a) : "l"(p));
    return a;
}
__device__ __forceinline__ uint32_t pack_bf16(float hi_src, float lo_src) {
    // result: lo16 = bf16(lo_src), hi16 = bf16(hi_src)
    uint32_t r;
    asm("cvt.rn.bf16x2.f32 %0, %1, %2;" : "=r"(r) : "f"(hi_src), "f"(lo_src));
    return r;
}
__device__ __forceinline__ void mma_bf16(float* d, uint32_t a0, uint32_t a1,
                                         uint32_t a2, uint32_t a3,
                                         uint32_t b0, uint32_t b1) {
    asm volatile(
        "mma.sync.aligned.m16n8k16.row.col.f32.bf16.bf16.f32 "
        "{%0,%1,%2,%3}, {%4,%5,%6,%7}, {%8,%9}, {%0,%1,%2,%3};"
        : "+f"(d[0]), "+f"(d[1]), "+f"(d[2]), "+f"(d[3])
        : "r"(a0), "r"(a1), "r"(a2), "r"(a3), "r"(b0), "r"(b1));
}

__global__ __cluster_dims__(8, 1, 1) __launch_bounds__(256, 1)
void rec_kernel(const float* __restrict__ Whh, const float* __restrict__ h0,
                float* __restrict__ hidden, float* __restrict__ hfinal,
                int t0)
{
    extern __shared__ float sm[];
    uint32_t* whi = (uint32_t*)sm + WHI_OFF;
    uint32_t* wlo = (uint32_t*)sm + WLO_OFF;
    float*    Hf  = sm + HF_OFF;           // [2][512][8] fp32
    uint32_t* hhi = (uint32_t*)sm + HHI_OFF;
    uint32_t* hlo = (uint32_t*)sm + HLO_OFF;
    float*    scr = sm + SCR_OFF;
    float*    stg = sm + STG_OFF;

    const int tid = threadIdx.x;
    uint32_t rank;
    asm("mov.u32 %0, %%cluster_ctarank;" : "=r"(rank));
    const int grp  = blockIdx.x >> 3;
    const int row0 = (int)rank * 64;
    const int b0   = grp * 8;

    // one-time W split: Whh[row0+r][2k2..2k2+1] -> packed hi/lo
    for (int idx = tid; idx < 64 * 256; idx += 256) {
        int r = idx >> 8, k2 = idx & 255;
        float2 wv = *(const float2*)&Whh[(size_t)(row0 + r) * N_HID + 2 * k2];
        uint32_t hw = pack_bf16(wv.y, wv.x);
        float ef = __uint_as_float(hw << 16);
        float of = __uint_as_float(hw & 0xffff0000u);
        uint32_t lw = pack_bf16(wv.y - of, wv.x - ef);
        whi[r * WPST + k2] = hw;
        wlo[r * WPST + k2] = lw;
    }
    // restore h(t0-1) -> Hf buffer (t0&1), layout [k][batch]
    {
        float* Hb = &Hf[(t0 & 1) * HT_SZ];
        for (int idx = tid; idx < 8 * 128; idx += 256) {
            int b = idx >> 7, k4 = (idx & 127) << 2;
            const float* src = (t0 == 0)
                ? &h0[(size_t)(b0 + b) * N_HID + k4]
                : &hidden[((size_t)(b0 + b) * LENGTH + (t0 - 1)) * N_HID + k4];
            float4 h = *(const float4*)src;
            Hb[(k4 + 0) * 8 + b] = h.x;
            Hb[(k4 + 1) * 8 + b] = h.y;
            Hb[(k4 + 2) * 8 + b] = h.z;
            Hb[(k4 + 3) * 8 + b] = h.w;
        }
    }

    const int w    = tid >> 5;
    const int lane = tid & 31;
    const int mt   = w & 3;
    const int kh   = w >> 2;
    const int g    = lane >> 2;
    const int tg   = lane & 3;

    // MMA operand base pointers (k2-indexed)
    const uint32_t* wh0 = whi + (mt * 16 + g) * WPST + kh * 128 + tg;
    const uint32_t* wh8 = wh0 + 8 * WPST;
    const uint32_t* wl0 = wlo + (mt * 16 + g) * WPST + kh * 128 + tg;
    const uint32_t* wl8 = wl0 + 8 * WPST;
    const uint32_t* bh  = hhi + (kh * 128 + tg) * 8 + g;
    const uint32_t* blo = hlo + (kh * 128 + tg) * 8 + g;

    // finalize coords (kh==0): rows rA=mt*16+g, rB=rA+8; batches 2tg, 2tg+1
    const int rA = mt * 16 + g;
    const int rB = rA + 8;
    const int absA = row0 + rA;
    const int absB = row0 + rB;
    const int ba = b0 + 2 * tg;

    // push decomposition: 1024 float4 = 8 ranks x 128 f4; 4/thread
    const int f4  = tid & 127;
    const int rb  = tid >> 7;
    const float* pSrc = &stg[f4 * 4];
    const uint32_t dOffBase = (uint32_t)((row0 * 8 + f4 * 4) * 4);

    uint32_t Hbase = smem_u32(Hf);
    uint32_t peer[8];
    #pragma unroll
    for (int r = 0; r < 8; r++)
        asm("mapa.shared::cluster.u32 %0, %1, %2;"
            : "=r"(peer[r]) : "r"(Hbase), "r"(r));

    __syncthreads();

    const int tend = t0 + T_SEG;
    for (int t = t0; t < tend; t++) {
        const int p = t & 1;
        const int q = p ^ 1;
        const float* Hp = &Hf[p * HT_SZ];

        // per-step H split: Hf[p] -> hhi/hlo packed (8 words/thread)
        #pragma unroll
        for (int i = 0; i < 8; i++) {
            int idx = tid + i * 256;        // = k2*8 + b
            int k2 = idx >> 3, b = idx & 7;
            float he = Hp[k2 * 16 + b];
            float ho = Hp[k2 * 16 + 8 + b];
            uint32_t hw = pack_bf16(ho, he);
            float ef = __uint_as_float(hw << 16);
            float of = __uint_as_float(hw & 0xffff0000u);
            uint32_t lw = pack_bf16(ho - of, he - ef);
            hhi[idx] = hw;
            hlo[idx] = lw;
        }
        __syncthreads();

        // Z prefetch (finalize warps) — hides under MMA
        float z0, z1, z2, z3;
        size_t offA0 = 0, offA1 = 0, offB0 = 0, offB1 = 0;
        if (kh == 0) {
            offA0 = ((size_t)ba * LENGTH + t) * N_HID + absA;
            offA1 = offA0 + (size_t)LENGTH * N_HID;
            offB0 = offA0 + 8;
            offB1 = offA1 + 8;
            z0 = hidden[offA0]; z1 = hidden[offA1];
            z2 = hidden[offB0]; z3 = hidden[offB1];
        }

        // MMA mainloop: 16 k16-steps, 3 bf16 MMAs each
        float acc0[4] = {0, 0, 0, 0};
        float acc1[4] = {0, 0, 0, 0};
        float acc2[4] = {0, 0, 0, 0};
        #pragma unroll 4
        for (int ks = 0; ks < 16; ks++) {
            uint32_t ah0 = wh0[ks * 8],     ah1 = wh8[ks * 8];
            uint32_t ah2 = wh0[ks * 8 + 4], ah3 = wh8[ks * 8 + 4];
            uint32_t al0 = wl0[ks * 8],     al1 = wl8[ks * 8];
            uint32_t al2 = wl0[ks * 8 + 4], al3 = wl8[ks * 8 + 4];
            uint32_t bh0 = bh[ks * 64],  bh1 = bh[ks * 64 + 32];
            uint32_t bl0 = blo[ks * 64], bl1 = blo[ks * 64 + 32];
            mma_bf16(acc0, ah0, ah1, ah2, ah3, bh0, bh1);
            mma_bf16(acc1, ah0, ah1, ah2, ah3, bl0, bl1);
            mma_bf16(acc2, al0, al1, al2, al3, bh0, bh1);
        }
        float c[4];
        #pragma unroll
        for (int i = 0; i < 4; i++) c[i] = acc0[i] + acc1[i] + acc2[i];

        // k-half reduce
        if (kh == 1)
            *(float4*)&scr[(mt * 32 + lane) * 4] =
                make_float4(c[0], c[1], c[2], c[3]);
        __syncthreads();

        if (kh == 0) {
            float4 o = *(const float4*)&scr[(mt * 32 + lane) * 4];
            c[0] += o.x; c[1] += o.y; c[2] += o.z; c[3] += o.w;

            float2 hA = *(const float2*)&Hp[absA * 8 + 2 * tg];
            float2 hB = *(const float2*)&Hp[absB * 8 + 2 * tg];
            float hn0 = 0.9f * hA.x + 0.1f * fmaxf(z0 + c[0], 0.0f);
            float hn1 = 0.9f * hA.y + 0.1f * fmaxf(z1 + c[1], 0.0f);
            float hn2 = 0.9f * hB.x + 0.1f * fmaxf(z2 + c[2], 0.0f);
            float hn3 = 0.9f * hB.y + 0.1f * fmaxf(z3 + c[3], 0.0f);

            *(float2*)&stg[rA * 8 + 2 * tg] = make_float2(hn0, hn1);
            *(float2*)&stg[rB * 8 + 2 * tg] = make_float2(hn2, hn3);
            z0 = hn0; z1 = hn1; z2 = hn2; z3 = hn3;
        }
        __syncthreads();

        // push stage (2KB) to all 8 ranks' Hf buffer q
        const uint32_t dOff = (uint32_t)(q * HT_SZ * 4) + dOffBase;
        float4 v4 = *(const float4*)pSrc;
        #pragma unroll
        for (int i = 0; i < 4; i++) {
            int r = rb + 2 * i;
            asm volatile("st.shared::cluster.v4.f32 [%0], {%1,%2,%3,%4};"
                         :: "r"(peer[r] + dOff),
                            "f"(v4.x), "f"(v4.y), "f"(v4.z), "f"(v4.w)
                         : "memory");
        }
        asm volatile("barrier.cluster.arrive.aligned;" ::: "memory");

        if (kh == 0) {
            hidden[offA0] = z0; hidden[offA1] = z1;
            hidden[offB0] = z2; hidden[offB1] = z3;
            if (t == LENGTH - 1) {
                hfinal[(size_t)ba * N_HID + absA] = z0;
                hfinal[(size_t)(ba + 1) * N_HID + absA] = z1;
                hfinal[(size_t)ba * N_HID + absB] = z2;
                hfinal[(size_t)(ba + 1) * N_HID + absB] = z3;
            }
        }
        asm volatile("barrier.cluster.wait.aligned;" ::: "memory");
    }
}

extern "C" void kernel_launch(void* const* d_in, const int* in_sizes, int n_in,
                              void* d_out, int out_size) {
    const float* u    = (const float*)d_in[0];
    const float* h0   = (const float*)d_in[1];
    const float* Win  = (const float*)d_in[2];
    const float* bin  = (const float*)d_in[3];
    const float* Wih  = (const float*)d_in[4];
    const float* bih  = (const float*)d_in[5];
    const float* Whh  = (const float*)d_in[6];
    const float* bhh  = (const float*)d_in[7];
    const float* Wout = (const float*)d_in[8];
    const float* bout = (const float*)d_in[9];

    float* out     = (float*)d_out;
    float* hidden  = out;
    float* outlist = out + OUT_LIST_OFF;
    float* hfinal  = out + OUT_FINAL_OFF;

    weff_kernel<<<N_HID, 128>>>(Wih, Win, bin, bih, bhh);

    {
        float* dWeff; float* dbeff;
        cudaGetSymbolAddress((void**)&dWeff, g_Weff);
        cudaGetSymbolAddress((void**)&dbeff, g_beff);
        dim3 grid(M_ROWS / 128, N_HID / 128);
        gemm_tn_bias<<<grid, 256>>>(u, dWeff, dbeff, hidden,
                                    M_ROWS, N_HID, N_IN);
    }

    {
        static int smem_set = 0;
        int smem = SM_WORDS * 4;   // 186368 B
        if (!smem_set) {
            cudaFuncSetAttribute(rec_kernel,
                                 cudaFuncAttributeMaxDynamicSharedMemorySize,
                                 smem);
            smem_set = 1;
        }
        for (int t0 = 0; t0 < LENGTH; t0 += T_SEG)
            rec_kernel<<<128, 256, smem>>>(Whh, h0, hidden, hfinal, t0);
    }

    {
        dim3 grid(M_ROWS / 128, N_OUT / 128);
        gemm_tn_bias<<<grid, 256>>>(hidden, Wout, bout, outlist,
                                    M_ROWS, N_OUT, N_HID);
    }
}

// round 13
// speedup vs baseline: 1.9016x; 1.0916x over previous
#include <cuda_runtime.h>
#include <cstdint>

#define N_IN   128
#define N_HID  512
#define N_OUT  128
#define BATCH  128
#define LENGTH 1024
#define M_ROWS (BATCH * LENGTH)
#define T_SEG  256

#define OUT_LIST_OFF  67108864ull
#define OUT_FINAL_OFF 83886080ull

__device__ float g_Weff[N_HID * N_IN];
__device__ float g_beff[N_HID];

// ---------------- W_eff = W_ih @ W_in ; b_eff = W_ih@b_in + b_ih + b_hh -----
__global__ void weff_kernel(const float* __restrict__ Wih,
                            const float* __restrict__ Win,
                            const float* __restrict__ bin,
                            const float* __restrict__ bih,
                            const float* __restrict__ bhh) {
    const int j = blockIdx.x;
    const int i = threadIdx.x;
    __shared__ float sred[128];

    float acc = 0.0f;
    #pragma unroll 8
    for (int k = 0; k < N_HID; k++)
        acc = fmaf(Wih[j * N_HID + k], Win[k * N_IN + i], acc);
    g_Weff[j * N_IN + i] = acc;

    float accb = 0.0f;
    for (int k = i; k < N_HID; k += 128)
        accb = fmaf(Wih[j * N_HID + k], bin[k], accb);
    sred[i] = accb;
    __syncthreads();
    for (int st = 64; st > 0; st >>= 1) {
        if (i < st) sred[i] += sred[i + st];
        __syncthreads();
    }
    if (i == 0) g_beff[j] = sred[0] + bih[j] + bhh[j];
}

// ---------------- C[m][n] = sum_k A[m][k]*B[n][k] + bias[n] -----------------
__global__ __launch_bounds__(256) void gemm_tn_bias(
    const float* __restrict__ A, const float* __restrict__ B,
    const float* __restrict__ bias, float* __restrict__ C,
    int M, int N, int K)
{
    __shared__ float As[8][132];
    __shared__ float Bs[8][132];

    const int tid = threadIdx.x;
    const int m0 = blockIdx.x * 128;
    const int n0 = blockIdx.y * 128;
    const int tx = tid & 15;
    const int ty = tid >> 4;
    const int lr = tid >> 1;
    const int lc = (tid & 1) << 2;

    float acc[8][8];
    #pragma unroll
    for (int i = 0; i < 8; i++)
        #pragma unroll
        for (int j = 0; j < 8; j++) acc[i][j] = 0.0f;

    const float* Ap = &A[(size_t)(m0 + lr) * K + lc];
    const float* Bp = &B[(size_t)(n0 + lr) * K + lc];

    for (int k0 = 0; k0 < K; k0 += 8) {
        float4 av = *(const float4*)&Ap[k0];
        float4 bv = *(const float4*)&Bp[k0];
        As[lc + 0][lr] = av.x; As[lc + 1][lr] = av.y;
        As[lc + 2][lr] = av.z; As[lc + 3][lr] = av.w;
        Bs[lc + 0][lr] = bv.x; Bs[lc + 1][lr] = bv.y;
        Bs[lc + 2][lr] = bv.z; Bs[lc + 3][lr] = bv.w;
        __syncthreads();

        #pragma unroll
        for (int kk = 0; kk < 8; kk++) {
            float4 a0 = *(const float4*)&As[kk][ty * 8];
            float4 a1 = *(const float4*)&As[kk][ty * 8 + 4];
            float4 b0 = *(const float4*)&Bs[kk][tx * 8];
            float4 b1 = *(const float4*)&Bs[kk][tx * 8 + 4];
            float ra[8] = {a0.x, a0.y, a0.z, a0.w, a1.x, a1.y, a1.z, a1.w};
            float rb[8] = {b0.x, b0.y, b0.z, b0.w, b1.x, b1.y, b1.z, b1.w};
            #pragma unroll
            for (int i = 0; i < 8; i++)
                #pragma unroll
                for (int j = 0; j < 8; j++)
                    acc[i][j] = fmaf(ra[i], rb[j], acc[i][j]);
        }
        __syncthreads();
    }

    float bs[8];
    #pragma unroll
    for (int j = 0; j < 8; j++) bs[j] = bias[n0 + tx * 8 + j];

    #pragma unroll
    for (int i = 0; i < 8; i++) {
        float* crow = &C[(size_t)(m0 + ty * 8 + i) * N + n0 + tx * 8];
        *(float4*)&crow[0] = make_float4(acc[i][0] + bs[0], acc[i][1] + bs[1],
                                         acc[i][2] + bs[2], acc[i][3] + bs[3]);
        *(float4*)&crow[4] = make_float4(acc[i][4] + bs[4], acc[i][5] + bs[5],
                                         acc[i][6] + bs[6], acc[i][7] + bs[7]);
    }
}

// ---------------- recurrence: bf16x3 mma, packed-bf16 exchange --------------
// 16 clusters x 8 CTAs x 256 threads. Warp w: m-tile mt=w&3, k-half kh=w>>2.
// W pre-split once into packed bf16 hi/lo [64][260]. h exchanged ALREADY
// SPLIT: finalize threads keep fp32 h in registers, pack bf16 hi/lo words
// (pairing rows via shfl_xor(4)), push packed words into peers' double-
// buffered hhi/hlo operand buffers. No per-step split phase.
#define WPST    260
#define WHI_OFF 0
#define WLO_OFF 16640
#define HHI_OFF 33280                 // uint32 [2][2048]  ([k2][batch])
#define HLO_OFF 37376                 // uint32 [2][2048]
#define SCR_OFF 41472                 // float  [512]
#define STG_OFF 41984                 // uint32 [512] (256 hi + 256 lo)
#define SM_WORDS 42496                // *4 = 169984 B

__device__ __forceinline__ uint32_t smem_u32(const void* p) {
    uint32_t a;
    asm("{ .reg .u64 t; cvta.to.shared.u64 t, %1; cvt.u32.u64 %0, t; }"
        : "=r"(a) : "l"(p));
    return a;
}
__device__ __forceinline__ uint32_t pack_bf16(float hi_src, float lo_src) {
    uint32_t r;
    asm("cvt.rn.bf16x2.f32 %0, %1, %2;" : "=r"(r) : "f"(hi_src), "f"(lo_src));
    return r;
}
__device__ __forceinline__ void mma_bf16(float* d, uint32_t a0, uint32_t a1,
                                         uint32_t a2, uint32_t a3,
                                         uint32_t b0, uint32_t b1) {
    asm volatile(
        "mma.sync.aligned.m16n8k16.row.col.f32.bf16.bf16.f32 "
        "{%0,%1,%2,%3}, {%4,%5,%6,%7}, {%8,%9}, {%0,%1,%2,%3};"
        : "+f"(d[0]), "+f"(d[1]), "+f"(d[2]), "+f"(d[3])
        : "r"(a0), "r"(a1), "r"(a2), "r"(a3), "r"(b0), "r"(b1));
}
__device__ __forceinline__ void split2(float e, float o,
                                       uint32_t& hiw, uint32_t& low) {
    hiw = pack_bf16(o, e);
    float ef = __uint_as_float(hiw << 16);
    float of = __uint_as_float(hiw & 0xffff0000u);
    low = pack_bf16(o - of, e - ef);
}

__global__ __cluster_dims__(8, 1, 1) __launch_bounds__(256, 1)
void rec_kernel(const float* __restrict__ Whh, const float* __restrict__ h0,
                float* __restrict__ hidden, float* __restrict__ hfinal,
                int t0)
{
    extern __shared__ float sm[];
    uint32_t* whi = (uint32_t*)sm + WHI_OFF;
    uint32_t* wlo = (uint32_t*)sm + WLO_OFF;
    uint32_t* hhi = (uint32_t*)sm + HHI_OFF;   // [2][2048]
    uint32_t* hlo = (uint32_t*)sm + HLO_OFF;   // [2][2048]
    float*    scr = sm + SCR_OFF;
    uint32_t* stg = (uint32_t*)sm + STG_OFF;   // [512]

    const int tid = threadIdx.x;
    uint32_t rank;
    asm("mov.u32 %0, %%cluster_ctarank;" : "=r"(rank));
    const int grp  = blockIdx.x >> 3;
    const int row0 = (int)rank * 64;
    const int b0   = grp * 8;

    // one-time W split
    for (int idx = tid; idx < 64 * 256; idx += 256) {
        int r = idx >> 8, k2 = idx & 255;
        float2 wv = *(const float2*)&Whh[(size_t)(row0 + r) * N_HID + 2 * k2];
        uint32_t hw, lw;
        split2(wv.x, wv.y, hw, lw);
        whi[r * WPST + k2] = hw;
        wlo[r * WPST + k2] = lw;
    }
    // init packed h buffers (ping t0&1) from h(t0-1): full 512 rows x 8 b
    {
        const int p0 = t0 & 1;
        for (int i = 0; i < 8; i++) {
            int idx = tid + i * 256;           // k2*8 + b
            int k2 = idx >> 3, b = idx & 7;
            const float* src = (t0 == 0)
                ? &h0[(size_t)(b0 + b) * N_HID + 2 * k2]
                : &hidden[((size_t)(b0 + b) * LENGTH + (t0 - 1)) * N_HID + 2 * k2];
            float2 h = *(const float2*)src;
            uint32_t hw, lw;
            split2(h.x, h.y, hw, lw);
            hhi[p0 * 2048 + idx] = hw;
            hlo[p0 * 2048 + idx] = lw;
        }
    }

    const int w    = tid >> 5;
    const int lane = tid & 31;
    const int mt   = w & 3;
    const int kh   = w >> 2;
    const int g    = lane >> 2;
    const int tg   = lane & 3;

    // MMA operand base pointers
    const uint32_t* wh0 = whi + (mt * 16 + g) * WPST + kh * 128 + tg;
    const uint32_t* wh8 = wh0 + 8 * WPST;
    const uint32_t* wl0 = wlo + (mt * 16 + g) * WPST + kh * 128 + tg;
    const uint32_t* wl8 = wl0 + 8 * WPST;
    const int bidx = (kh * 128 + tg) * 8 + g;

    // finalize coords (kh==0): rows rA, rB; batches ba, ba+1
    const int rA = mt * 16 + g;
    const int rB = rA + 8;
    const int absA = row0 + rA;
    const int absB = row0 + rB;
    const int ba = b0 + 2 * tg;
    const bool evg = ((g & 1) == 0);
    const int lk2A = mt * 8 + (g >> 1);       // local k2 for rows rA,rA+1
    const int lk2B = lk2A + 4;

    // h_old registers (kh==0 threads)
    float hr0 = 0, hr1 = 0, hr2 = 0, hr3 = 0;
    if (kh == 0) {
        const float* s0 = (t0 == 0)
            ? &h0[(size_t)ba * N_HID]
            : &hidden[((size_t)ba * LENGTH + (t0 - 1)) * N_HID];
        const float* s1 = (t0 == 0)
            ? &h0[(size_t)(ba + 1) * N_HID]
            : &hidden[((size_t)(ba + 1) * LENGTH + (t0 - 1)) * N_HID];
        hr0 = s0[absA]; hr1 = s1[absA];
        hr2 = s0[absB]; hr3 = s1[absB];
    }

    // push decomposition: 1024 v4 = 8 ranks x 128 f4 (64 hi + 64 lo); 4/thread
    const int f   = tid & 127;
    const int rb  = tid >> 7;
    const uint32_t* pSrc = stg + f * 4;
    const uint32_t dOffBaseW =
        (uint32_t)((f < 64) ? (row0 * 4 + f * 4)
                            : (4096 + row0 * 4 + (f - 64) * 4));

    uint32_t Hbase = smem_u32(hhi);
    uint32_t peer[8];
    #pragma unroll
    for (int r = 0; r < 8; r++)
        asm("mapa.shared::cluster.u32 %0, %1, %2;"
            : "=r"(peer[r]) : "r"(Hbase), "r"(r));

    __syncthreads();

    const int tend = t0 + T_SEG;
    for (int t = t0; t < tend; t++) {
        const int p = t & 1;
        const int q = p ^ 1;
        const uint32_t* bh  = hhi + p * 2048 + bidx;
        const uint32_t* bl  = hlo + p * 2048 + bidx;

        // Z prefetch (finalize warps) — hides under MMA
        float z0, z1, z2, z3;
        size_t offA0 = 0, offA1 = 0, offB0 = 0, offB1 = 0;
        if (kh == 0) {
            offA0 = ((size_t)ba * LENGTH + t) * N_HID + absA;
            offA1 = offA0 + (size_t)LENGTH * N_HID;
            offB0 = offA0 + 8;
            offB1 = offA1 + 8;
            z0 = hidden[offA0]; z1 = hidden[offA1];
            z2 = hidden[offB0]; z3 = hidden[offB1];
        }

        // MMA mainloop
        float acc0[4] = {0, 0, 0, 0};
        float acc1[4] = {0, 0, 0, 0};
        float acc2[4] = {0, 0, 0, 0};
        #pragma unroll 4
        for (int ks = 0; ks < 16; ks++) {
            uint32_t ah0 = wh0[ks * 8],     ah1 = wh8[ks * 8];
            uint32_t ah2 = wh0[ks * 8 + 4], ah3 = wh8[ks * 8 + 4];
            uint32_t al0 = wl0[ks * 8],     al1 = wl8[ks * 8];
            uint32_t al2 = wl0[ks * 8 + 4], al3 = wl8[ks * 8 + 4];
            uint32_t bh0 = bh[ks * 64], bh1 = bh[ks * 64 + 32];
            uint32_t bl0 = bl[ks * 64], bl1 = bl[ks * 64 + 32];
            mma_bf16(acc0, ah0, ah1, ah2, ah3, bh0, bh1);
            mma_bf16(acc1, ah0, ah1, ah2, ah3, bl0, bl1);
            mma_bf16(acc2, al0, al1, al2, al3, bh0, bh1);
        }
        float c[4];
        #pragma unroll
        for (int i = 0; i < 4; i++) c[i] = acc0[i] + acc1[i] + acc2[i];

        // k-half reduce
        if (kh == 1)
            *(float4*)&scr[(mt * 32 + lane) * 4] =
                make_float4(c[0], c[1], c[2], c[3]);
        __syncthreads();

        if (kh == 0) {
            float4 o = *(const float4*)&scr[(mt * 32 + lane) * 4];
            float hn0 = 0.9f * hr0 + 0.1f * fmaxf(z0 + c[0] + o.x, 0.0f);
            float hn1 = 0.9f * hr1 + 0.1f * fmaxf(z1 + c[1] + o.y, 0.0f);
            float hn2 = 0.9f * hr2 + 0.1f * fmaxf(z2 + c[2] + o.z, 0.0f);
            float hn3 = 0.9f * hr3 + 0.1f * fmaxf(z3 + c[3] + o.w, 0.0f);
            hr0 = hn0; hr1 = hn1; hr2 = hn2; hr3 = hn3;

            // pair adjacent rows (g ^ 1) and pack bf16 hi/lo
            float pn0 = __shfl_xor_sync(0xffffffffu, hn0, 4);
            float pn1 = __shfl_xor_sync(0xffffffffu, hn1, 4);
            float pn2 = __shfl_xor_sync(0xffffffffu, hn2, 4);
            float pn3 = __shfl_xor_sync(0xffffffffu, hn3, 4);
            if (evg) {
                uint32_t hw, lw;
                split2(hn0, pn0, hw, lw);
                stg[lk2A * 8 + 2 * tg] = hw;  stg[256 + lk2A * 8 + 2 * tg] = lw;
                split2(hn1, pn1, hw, lw);
                stg[lk2A * 8 + 2 * tg + 1] = hw;
                stg[256 + lk2A * 8 + 2 * tg + 1] = lw;
                split2(hn2, pn2, hw, lw);
                stg[lk2B * 8 + 2 * tg] = hw;  stg[256 + lk2B * 8 + 2 * tg] = lw;
                split2(hn3, pn3, hw, lw);
                stg[lk2B * 8 + 2 * tg + 1] = hw;
                stg[256 + lk2B * 8 + 2 * tg + 1] = lw;
            }
            z0 = hn0; z1 = hn1; z2 = hn2; z3 = hn3;
        }
        __syncthreads();

        // push packed stage (2KB) into all 8 ranks' buffer q
        const uint32_t dOff = (dOffBaseW + (uint32_t)q * 2048u) * 4u;
        uint4 v4 = *(const uint4*)pSrc;
        #pragma unroll
        for (int i = 0; i < 4; i++) {
            int r = rb + 2 * i;
            asm volatile("st.shared::cluster.v4.b32 [%0], {%1,%2,%3,%4};"
                         :: "r"(peer[r] + dOff),
                            "r"(v4.x), "r"(v4.y), "r"(v4.z), "r"(v4.w)
                         : "memory");
        }
        asm volatile("barrier.cluster.arrive.aligned;" ::: "memory");

        // global stores in barrier-drain shadow
        if (kh == 0) {
            hidden[offA0] = z0; hidden[offA1] = z1;
            hidden[offB0] = z2; hidden[offB1] = z3;
            if (t == LENGTH - 1) {
                hfinal[(size_t)ba * N_HID + absA] = z0;
                hfinal[(size_t)(ba + 1) * N_HID + absA] = z1;
                hfinal[(size_t)ba * N_HID + absB] = z2;
                hfinal[(size_t)(ba + 1) * N_HID + absB] = z3;
            }
        }
        asm volatile("barrier.cluster.wait.aligned;" ::: "memory");
    }
}

extern "C" void kernel_launch(void* const* d_in, const int* in_sizes, int n_in,
                              void* d_out, int out_size) {
    const float* u    = (const float*)d_in[0];
    const float* h0   = (const float*)d_in[1];
    const float* Win  = (const float*)d_in[2];
    const float* bin  = (const float*)d_in[3];
    const float* Wih  = (const float*)d_in[4];
    const float* bih  = (const float*)d_in[5];
    const float* Whh  = (const float*)d_in[6];
    const float* bhh  = (const float*)d_in[7];
    const float* Wout = (const float*)d_in[8];
    const float* bout = (const float*)d_in[9];

    float* out     = (float*)d_out;
    float* hidden  = out;
    float* outlist = out + OUT_LIST_OFF;
    float* hfinal  = out + OUT_FINAL_OFF;

    weff_kernel<<<N_HID, 128>>>(Wih, Win, bin, bih, bhh);

    {
        float* dWeff; float* dbeff;
        cudaGetSymbolAddress((void**)&dWeff, g_Weff);
        cudaGetSymbolAddress((void**)&dbeff, g_beff);
        dim3 grid(M_ROWS / 128, N_HID / 128);
        gemm_tn_bias<<<grid, 256>>>(u, dWeff, dbeff, hidden,
                                    M_ROWS, N_HID, N_IN);
    }

    {
        static int smem_set = 0;
        int smem = SM_WORDS * 4;   // 169984 B
        if (!smem_set) {
            cudaFuncSetAttribute(rec_kernel,
                                 cudaFuncAttributeMaxDynamicSharedMemorySize,
                                 smem);
            smem_set = 1;
        }
        for (int t0 = 0; t0 < LENGTH; t0 += T_SEG)
            rec_kernel<<<128, 256, smem>>>(Whh, h0, hidden, hfinal, t0);
    }

    {
        dim3 grid(M_ROWS / 128, N_OUT / 128);
        gemm_tn_bias<<<grid, 256>>>(hidden, Wout, bout, outlist,
                                    M_ROWS, N_OUT, N_HID);
    }
}